// round 1
// baseline (speedup 1.0000x reference)
#include <cuda_runtime.h>
#include <math.h>

#define Bb   8
#define LEAF 1024
#define Nn   2048
#define Dd   128
#define BN   (Bb * Nn)   // 16384

// Scratch (allocation-free rule: device globals)
__device__ float g_nf[BN * Dd];    // raw node features (tree means, no enc)
__device__ float g_h[BN * Dd];     // gelu(LN(x))
__device__ float g_agg[BN * Dd];   // mean aggregation
__device__ int   g_off[BN + 1];    // CSR offsets into edge list

// ---------------------------------------------------------------------------
// Tree build: pairwise mean up-sweep. Each thread owns one feature dim d.
// reduce_store: given 32 values at (base, off), write 5 levels of parents.
// ---------------------------------------------------------------------------
__device__ __forceinline__ void reduce_store(const float v32[32], int bN, int base, int off, int d) {
    float v16[16];
#pragma unroll
    for (int j = 0; j < 16; j++) {
        v16[j] = 0.5f * (v32[2*j] + v32[2*j+1]);
        g_nf[(bN + (base >> 1) + (off >> 1) + j) * Dd + d] = v16[j];
    }
    float v8[8];
#pragma unroll
    for (int j = 0; j < 8; j++) {
        v8[j] = 0.5f * (v16[2*j] + v16[2*j+1]);
        g_nf[(bN + (base >> 2) + (off >> 2) + j) * Dd + d] = v8[j];
    }
    float v4[4];
#pragma unroll
    for (int j = 0; j < 4; j++) {
        v4[j] = 0.5f * (v8[2*j] + v8[2*j+1]);
        g_nf[(bN + (base >> 3) + (off >> 3) + j) * Dd + d] = v4[j];
    }
    float v2[2];
#pragma unroll
    for (int j = 0; j < 2; j++) {
        v2[j] = 0.5f * (v4[2*j] + v4[2*j+1]);
        g_nf[(bN + (base >> 4) + (off >> 4) + j) * Dd + d] = v2[j];
    }
    float v1 = 0.5f * (v2[0] + v2[1]);
    g_nf[(bN + (base >> 5) + (off >> 5)) * Dd + d] = v1;
}

// Stage 1: each block = (batch b, 32-leaf subtree s). Writes leaf nodes
// (1024 + s*32 + j) and internal levels down to nodes 32..63.
__global__ void tree1_kernel(const float* __restrict__ elements) {
    int b = blockIdx.x >> 5;
    int s = blockIdx.x & 31;
    int d = threadIdx.x;
    int bN = b * Nn;
    float v32[32];
#pragma unroll
    for (int j = 0; j < 32; j++) {
        float v = elements[(b * LEAF + s * 32 + j) * Dd + d];
        v32[j] = v;
        g_nf[(bN + LEAF + s * 32 + j) * Dd + d] = v;
    }
    reduce_store(v32, bN, 1024, s * 32, d);
}

// Stage 2: one block per batch; reduce nodes 32..63 up to node 1; write node 0.
__global__ void tree2_kernel() {
    int b = blockIdx.x;
    int d = threadIdx.x;
    int bN = b * Nn;
    float v32[32];
#pragma unroll
    for (int j = 0; j < 32; j++)
        v32[j] = g_nf[(bN + 32 + j) * Dd + d];
    reduce_store(v32, bN, 32, 0, d);
    g_nf[bN * Dd + d] = -1.0f;  // global node 0
}

// ---------------------------------------------------------------------------
// x = nf + positional encoding (exact integer-derived vpos/hpos)
// ---------------------------------------------------------------------------
__global__ void encx_kernel(float* __restrict__ x) {
    int gi = blockIdx.x;          // global node 0..BN-1
    int node = gi & (Nn - 1);
    int d = threadIdx.x;
    float pos;
    if (node == 0) {
        pos = (d < 64) ? -0.5f : -1.0f;   // hpos = -0.5, vpos = -1
    } else {
        int vp = 31 - __clz(node);
        pos = (d < 64) ? (float)(node - (1 << vp)) : (float)vp;
    }
    int dd = d & 63;
    int k = dd >> 1;
    // inv = exp(-k * ln(10000)/32)
    float inv = expf(-0.28782313662425574f * (float)k);
    float ang = pos * inv;
    float e = (dd & 1) ? cosf(ang) : sinf(ang);
    x[gi * Dd + d] = g_nf[gi * Dd + d] + e;
}

// ---------------------------------------------------------------------------
// CSR offsets: dst array is globally nondecreasing by construction.
// off[i] = lower_bound(dst, i)
// ---------------------------------------------------------------------------
__global__ void offsets_kernel(const int* __restrict__ dst, int E) {
    int i = blockIdx.x * blockDim.x + threadIdx.x;
    if (i > BN) return;
    int lo = 0, hi = E;
    while (lo < hi) {
        int mid = (lo + hi) >> 1;
        if (dst[mid] < i) lo = mid + 1; else hi = mid;
    }
    g_off[i] = lo;
}

// ---------------------------------------------------------------------------
// h = gelu_exact(LayerNorm(x) * gamma + beta); one block per node
// ---------------------------------------------------------------------------
__global__ void ln_gelu_kernel(const float* __restrict__ x,
                               const float* __restrict__ gamma,
                               const float* __restrict__ beta) {
    int i = blockIdx.x;
    int d = threadIdx.x;
    float v = x[i * Dd + d];
    float s = v, s2 = v * v;
#pragma unroll
    for (int o = 16; o; o >>= 1) {
        s  += __shfl_xor_sync(0xffffffffu, s, o);
        s2 += __shfl_xor_sync(0xffffffffu, s2, o);
    }
    __shared__ float ss[4], ss2[4];
    int w = d >> 5, lane = d & 31;
    if (lane == 0) { ss[w] = s; ss2[w] = s2; }
    __syncthreads();
    s  = ss[0] + ss[1] + ss[2] + ss[3];
    s2 = ss2[0] + ss2[1] + ss2[2] + ss2[3];
    float mu  = s * (1.0f / 128.0f);
    float var = s2 * (1.0f / 128.0f) - mu * mu;
    float t = (v - mu) * rsqrtf(var + 1e-5f) * gamma[d] + beta[d];
    float g = 0.5f * t * (1.0f + erff(t * 0.70710678118654752f));
    g_h[i * Dd + d] = g;
}

// ---------------------------------------------------------------------------
// agg[i] = mean over in-edges of h[src]; one block (128 threads) per dst node
// ---------------------------------------------------------------------------
__global__ void agg_kernel(const int* __restrict__ src) {
    int i = blockIdx.x;
    int d = threadIdx.x;
    int s = g_off[i], e = g_off[i + 1];
    float a0 = 0.f, a1 = 0.f, a2 = 0.f, a3 = 0.f;
    int t = s;
    for (; t + 4 <= e; t += 4) {
        int i0 = __ldg(&src[t]);
        int i1 = __ldg(&src[t + 1]);
        int i2 = __ldg(&src[t + 2]);
        int i3 = __ldg(&src[t + 3]);
        a0 += g_h[i0 * Dd + d];
        a1 += g_h[i1 * Dd + d];
        a2 += g_h[i2 * Dd + d];
        a3 += g_h[i3 * Dd + d];
    }
    for (; t < e; t++) a0 += g_h[__ldg(&src[t]) * Dd + d];
    float acc = (a0 + a1) + (a2 + a3);
    int cnt = e - s;
    float deg = (float)(cnt > 0 ? cnt : 1);
    g_agg[i * Dd + d] = acc / deg;
}

// ---------------------------------------------------------------------------
// x += agg @ w_nei + b_nei + h @ w_root
// Register-blocked fp32 GEMM: BM=64, BN=128(full), BK=8, per-thread 8x4.
// Two K-passes: (g_agg, w_nei) then (g_h, w_root).
// ---------------------------------------------------------------------------
__global__ void gemm_kernel(const float* __restrict__ W1,   // w_nei[l]
                            const float* __restrict__ W2,   // w_root[l]
                            const float* __restrict__ bias, // b_nei[l]
                            float* __restrict__ X) {
    const int BM = 64, BK = 8;
    __shared__ float As[BK][BM];
    __shared__ float Bs[BK][Dd];
    int block_m = blockIdx.x * BM;
    int tid = threadIdx.x;                 // 0..255
    int tm = (tid >> 5) * 8;               // row offset 0..56
    int tn = (tid & 31) * 4;               // col offset 0..124

    float acc[8][4];
#pragma unroll
    for (int i = 0; i < 8; i++)
#pragma unroll
        for (int j = 0; j < 4; j++) acc[i][j] = 0.f;

#pragma unroll
    for (int pass = 0; pass < 2; pass++) {
        const float* A = pass ? g_h : g_agg;
        const float* W = pass ? W2 : W1;
        for (int k0 = 0; k0 < Dd; k0 += BK) {
            // A tile -> As[kk][m]
#pragma unroll
            for (int e = tid; e < BM * BK; e += 256) {
                int m = e >> 3, kk = e & 7;
                As[kk][m] = A[(block_m + m) * Dd + k0 + kk];
            }
            // B tile -> Bs[kk][n], float4
            {
                int kk = tid >> 5;
                int n4 = (tid & 31) * 4;
                float4 w = *(const float4*)&W[(k0 + kk) * Dd + n4];
                *(float4*)&Bs[kk][n4] = w;
            }
            __syncthreads();
#pragma unroll
            for (int kk = 0; kk < BK; kk++) {
                float a[8], bq[4];
                float4 a0 = *(const float4*)&As[kk][tm];
                float4 a1 = *(const float4*)&As[kk][tm + 4];
                a[0]=a0.x; a[1]=a0.y; a[2]=a0.z; a[3]=a0.w;
                a[4]=a1.x; a[5]=a1.y; a[6]=a1.z; a[7]=a1.w;
                float4 b0 = *(const float4*)&Bs[kk][tn];
                bq[0]=b0.x; bq[1]=b0.y; bq[2]=b0.z; bq[3]=b0.w;
#pragma unroll
                for (int i = 0; i < 8; i++)
#pragma unroll
                    for (int j = 0; j < 4; j++)
                        acc[i][j] += a[i] * bq[j];
            }
            __syncthreads();
        }
    }
    // epilogue: x += acc + bias
    float4 bb = *(const float4*)&bias[tn];
#pragma unroll
    for (int i = 0; i < 8; i++) {
        float* xp = &X[(block_m + tm + i) * Dd + tn];
        float4 xv = *(float4*)xp;
        xv.x += acc[i][0] + bb.x;
        xv.y += acc[i][1] + bb.y;
        xv.z += acc[i][2] + bb.z;
        xv.w += acc[i][3] + bb.w;
        *(float4*)xp = xv;
    }
}

// ---------------------------------------------------------------------------
extern "C" void kernel_launch(void* const* d_in, const int* in_sizes, int n_in,
                              void* d_out, int out_size) {
    const float* elements = (const float*)d_in[0];
    const float* ln_gamma = (const float*)d_in[1];
    const float* ln_beta  = (const float*)d_in[2];
    const float* w_nei    = (const float*)d_in[3];
    const float* b_nei    = (const float*)d_in[4];
    const float* w_root   = (const float*)d_in[5];
    const int*   edges    = (const int*)d_in[6];
    float* x = (float*)d_out;

    int E = in_sizes[6] / 2;
    const int* src = edges;
    const int* dst = edges + E;

    tree1_kernel<<<Bb * 32, Dd>>>(elements);
    tree2_kernel<<<Bb, Dd>>>();
    encx_kernel<<<BN, Dd>>>(x);
    offsets_kernel<<<(BN + 1 + 127) / 128, 128>>>(dst, E);

    for (int l = 0; l < 2; l++) {
        ln_gelu_kernel<<<BN, Dd>>>(x, ln_gamma + l * Dd, ln_beta + l * Dd);
        agg_kernel<<<BN, Dd>>>(src);
        gemm_kernel<<<BN / 64, 256>>>(w_nei + l * Dd * Dd,
                                      w_root + l * Dd * Dd,
                                      b_nei + l * Dd, x);
    }
}

// round 2
// speedup vs baseline: 2.5195x; 2.5195x over previous
#include <cuda_runtime.h>
#include <math.h>

#define Bb   8
#define LEAF 1024
#define Nn   2048
#define Dd   128
#define BN   (Bb * Nn)      // 16384
#define HEAVY_PER_B 15      // nodes 1..15 per batch have deg > 128
#define HCHUNKS 16          // 16 chunks x 128 edges covers deg <= 2048
#define HEAVY_W (Bb * HEAVY_PER_B * HCHUNKS)   // 1920

// Scratch (allocation-free rule: device globals)
__device__ float g_nf[BN * Dd];          // raw node features (tree means)
__device__ float g_h[BN * Dd];           // gelu(LN(x))
__device__ float g_agg[BN * Dd];         // mean aggregation
__device__ float g_part[HEAVY_W * Dd];   // heavy-node partial sums
__device__ int   g_off[BN + 1];          // CSR offsets into edge list

// ---------------------------------------------------------------------------
// f32x2 packed helpers (SASS FFMA2 — PTX-only, ptxas won't auto-fuse)
// ---------------------------------------------------------------------------
__device__ __forceinline__ unsigned long long pack2(float lo, float hi) {
    unsigned long long r;
    asm("mov.b64 %0, {%1, %2};" : "=l"(r) : "f"(lo), "f"(hi));
    return r;
}
__device__ __forceinline__ void unpack2(unsigned long long v, float& lo, float& hi) {
    asm("mov.b64 {%0, %1}, %2;" : "=f"(lo), "=f"(hi) : "l"(v));
}
__device__ __forceinline__ void ffma2(unsigned long long& d,
                                      unsigned long long a,
                                      unsigned long long b) {
    asm("fma.rn.f32x2 %0, %1, %2, %0;" : "+l"(d) : "l"(a), "l"(b));
}

// ---------------------------------------------------------------------------
// Tree build: pairwise mean up-sweep. Each thread owns one feature dim d.
// ---------------------------------------------------------------------------
__device__ __forceinline__ void reduce_store(const float v32[32], int bN, int base, int off, int d) {
    float v16[16];
#pragma unroll
    for (int j = 0; j < 16; j++) {
        v16[j] = 0.5f * (v32[2*j] + v32[2*j+1]);
        g_nf[(bN + (base >> 1) + (off >> 1) + j) * Dd + d] = v16[j];
    }
    float v8[8];
#pragma unroll
    for (int j = 0; j < 8; j++) {
        v8[j] = 0.5f * (v16[2*j] + v16[2*j+1]);
        g_nf[(bN + (base >> 2) + (off >> 2) + j) * Dd + d] = v8[j];
    }
    float v4[4];
#pragma unroll
    for (int j = 0; j < 4; j++) {
        v4[j] = 0.5f * (v8[2*j] + v8[2*j+1]);
        g_nf[(bN + (base >> 3) + (off >> 3) + j) * Dd + d] = v4[j];
    }
    float v2[2];
#pragma unroll
    for (int j = 0; j < 2; j++) {
        v2[j] = 0.5f * (v4[2*j] + v4[2*j+1]);
        g_nf[(bN + (base >> 4) + (off >> 4) + j) * Dd + d] = v2[j];
    }
    float v1 = 0.5f * (v2[0] + v2[1]);
    g_nf[(bN + (base >> 5) + (off >> 5)) * Dd + d] = v1;
}

__global__ void tree1_kernel(const float* __restrict__ elements) {
    int b = blockIdx.x >> 5;
    int s = blockIdx.x & 31;
    int d = threadIdx.x;
    int bN = b * Nn;
    float v32[32];
#pragma unroll
    for (int j = 0; j < 32; j++) {
        float v = elements[(b * LEAF + s * 32 + j) * Dd + d];
        v32[j] = v;
        g_nf[(bN + LEAF + s * 32 + j) * Dd + d] = v;
    }
    reduce_store(v32, bN, 1024, s * 32, d);
}

__global__ void tree2_kernel() {
    int b = blockIdx.x;
    int d = threadIdx.x;
    int bN = b * Nn;
    float v32[32];
#pragma unroll
    for (int j = 0; j < 32; j++)
        v32[j] = g_nf[(bN + 32 + j) * Dd + d];
    reduce_store(v32, bN, 32, 0, d);
    g_nf[bN * Dd + d] = -1.0f;  // global node 0
}

// ---------------------------------------------------------------------------
// x = nf + positional encoding; fused LN + exact GELU -> g_h (layer 0 input)
// ---------------------------------------------------------------------------
__global__ void encx_kernel(float* __restrict__ x,
                            const float* __restrict__ gamma,
                            const float* __restrict__ beta) {
    int gi = blockIdx.x;
    int node = gi & (Nn - 1);
    int d = threadIdx.x;
    float pos;
    if (node == 0) {
        pos = (d < 64) ? -0.5f : -1.0f;
    } else {
        int vp = 31 - __clz(node);
        pos = (d < 64) ? (float)(node - (1 << vp)) : (float)vp;
    }
    int dd = d & 63;
    int k = dd >> 1;
    float inv = expf(-0.28782313662425574f * (float)k);   // exp(-k*ln1e4/32)
    float ang = pos * inv;
    float e = (dd & 1) ? cosf(ang) : sinf(ang);
    float v = g_nf[gi * Dd + d] + e;
    x[gi * Dd + d] = v;

    // LayerNorm + GELU
    float s = v, s2 = v * v;
#pragma unroll
    for (int o = 16; o; o >>= 1) {
        s  += __shfl_xor_sync(0xffffffffu, s, o);
        s2 += __shfl_xor_sync(0xffffffffu, s2, o);
    }
    __shared__ float ss[4], ss2[4];
    int w = d >> 5, lane = d & 31;
    if (lane == 0) { ss[w] = s; ss2[w] = s2; }
    __syncthreads();
    s  = ss[0] + ss[1] + ss[2] + ss[3];
    s2 = ss2[0] + ss2[1] + ss2[2] + ss2[3];
    float mu  = s * (1.0f / 128.0f);
    float var = s2 * (1.0f / 128.0f) - mu * mu;
    float t = (v - mu) * rsqrtf(var + 1e-5f) * gamma[d] + beta[d];
    g_h[gi * Dd + d] = 0.5f * t * (1.0f + erff(t * 0.70710678118654752f));
}

// ---------------------------------------------------------------------------
// CSR offsets: edge-parallel boundary detection (dst globally nondecreasing)
// ---------------------------------------------------------------------------
__global__ void offsets_kernel(const int* __restrict__ dst, int E) {
    int e = blockIdx.x * blockDim.x + threadIdx.x;
    if (e >= E) return;
    int d1 = dst[e];
    int d0 = (e == 0) ? -1 : dst[e - 1];
    for (int i = d0 + 1; i <= d1; i++) g_off[i] = e;
    if (e == E - 1)
        for (int i = d1 + 1; i <= BN; i++) g_off[i] = E;
}

// ---------------------------------------------------------------------------
// Aggregation: float4 gather, 4 edge-groups per block.
//   blocks [0, BN):       one node each (skipping heavy nodes local 1..15)
//   blocks [BN, BN+1920): heavy-node 128-edge chunks -> g_part
// ---------------------------------------------------------------------------
__global__ void agg_kernel(const int* __restrict__ src) {
    __shared__ float sbuf[4 * Dd];
    int bid = blockIdx.x;
    int tid = threadIdx.x;
    int g = tid >> 5, l = tid & 31;
    int s, e;
    float scale;
    float* out;
    if (bid < BN) {
        int i = bid;
        int local = i & (Nn - 1);
        if (local >= 1 && local <= HEAVY_PER_B) return;   // heavy path handles
        s = g_off[i];
        e = g_off[i + 1];
        int deg = e - s;
        scale = 1.0f / (float)(deg > 0 ? deg : 1);
        out = &g_agg[i * Dd];
    } else {
        int w = bid - BN;
        int b = w / (HEAVY_PER_B * HCHUNKS);
        int r = w % (HEAVY_PER_B * HCHUNKS);
        int local = 1 + (r >> 4);
        int c = r & 15;
        int i = b * Nn + local;
        int s0 = g_off[i], e0 = g_off[i + 1];
        s = s0 + c * 128;
        e = min(e0, s + 128);
        if (e < s) e = s;
        scale = 1.0f;
        out = &g_part[w * Dd];
    }
    float4 acc = make_float4(0.f, 0.f, 0.f, 0.f);
    int t = s + g;
    for (; t + 4 < e; t += 8) {
        int i0 = __ldg(&src[t]);
        int i1 = __ldg(&src[t + 4]);
        float4 v0 = *(const float4*)&g_h[i0 * Dd + l * 4];
        float4 v1 = *(const float4*)&g_h[i1 * Dd + l * 4];
        acc.x += v0.x + v1.x;
        acc.y += v0.y + v1.y;
        acc.z += v0.z + v1.z;
        acc.w += v0.w + v1.w;
    }
    if (t < e) {
        int i0 = __ldg(&src[t]);
        float4 v0 = *(const float4*)&g_h[i0 * Dd + l * 4];
        acc.x += v0.x; acc.y += v0.y; acc.z += v0.z; acc.w += v0.w;
    }
    *(float4*)&sbuf[g * Dd + l * 4] = acc;
    __syncthreads();
    float v = sbuf[tid] + sbuf[Dd + tid] + sbuf[2 * Dd + tid] + sbuf[3 * Dd + tid];
    out[tid] = v * scale;
}

// Deterministic fixup: sum the 16 partials of each heavy node in fixed order.
__global__ void aggfix_kernel() {
    int b = blockIdx.x / HEAVY_PER_B;
    int r = blockIdx.x % HEAVY_PER_B;
    int local = r + 1;
    int i = b * Nn + local;
    int t = threadIdx.x;
    float sum = 0.f;
#pragma unroll
    for (int c = 0; c < HCHUNKS; c++)
        sum += g_part[(b * HEAVY_PER_B * HCHUNKS + r * HCHUNKS + c) * Dd + t];
    int deg = g_off[i + 1] - g_off[i];
    g_agg[i * Dd + t] = sum / (float)(deg > 0 ? deg : 1);
}

// ---------------------------------------------------------------------------
// x += agg @ W1 + bias + h @ W2, f32x2 packed FMA.
// BM=64, BN=128 (full), BK=32, 128 threads, 8x8 micro-tile.
// FUSE: epilogue computes next layer's h = gelu(LN(x_new)) into g_h.
// ---------------------------------------------------------------------------
template<bool FUSE>
__global__ void __launch_bounds__(128) gemm_kernel(
    const float* __restrict__ W1, const float* __restrict__ W2,
    const float* __restrict__ bias,
    const float* __restrict__ gamma, const float* __restrict__ beta,
    float* __restrict__ X)
{
    __shared__ float As[32][64];
    __shared__ float Bs[32][128];
    const int bm = blockIdx.x * 64;
    const int tid = threadIdx.x;
    const int trow = tid >> 4;   // 0..7
    const int tcol = tid & 15;   // 0..15
    const int tm = trow * 8;
    const int tn = tcol * 8;

    unsigned long long acc[8][4];
#pragma unroll
    for (int i = 0; i < 8; i++)
#pragma unroll
        for (int j = 0; j < 4; j++) acc[i][j] = 0ull;

#pragma unroll
    for (int pass = 0; pass < 2; pass++) {
        const float* A = pass ? g_h : g_agg;
        const float* W = pass ? W2 : W1;
#pragma unroll
        for (int k0 = 0; k0 < Dd; k0 += 32) {
            // A tile [64 x 32] -> As[kk][m]
            {
                int m = tid >> 1, half = tid & 1;
                const float* ap = &A[(bm + m) * Dd + k0 + half * 16];
                float4 v0 = *(const float4*)(ap);
                float4 v1 = *(const float4*)(ap + 4);
                float4 v2 = *(const float4*)(ap + 8);
                float4 v3 = *(const float4*)(ap + 12);
                int kb = half * 16;
                As[kb+ 0][m] = v0.x; As[kb+ 1][m] = v0.y; As[kb+ 2][m] = v0.z; As[kb+ 3][m] = v0.w;
                As[kb+ 4][m] = v1.x; As[kb+ 5][m] = v1.y; As[kb+ 6][m] = v1.z; As[kb+ 7][m] = v1.w;
                As[kb+ 8][m] = v2.x; As[kb+ 9][m] = v2.y; As[kb+10][m] = v2.z; As[kb+11][m] = v2.w;
                As[kb+12][m] = v3.x; As[kb+13][m] = v3.y; As[kb+14][m] = v3.z; As[kb+15][m] = v3.w;
            }
            // B tile [32 x 128] -> Bs[kk][n]
            {
                int kk = tid >> 2, q = tid & 3;
                const float* wp = &W[(k0 + kk) * Dd + q * 32];
#pragma unroll
                for (int j = 0; j < 8; j++)
                    *(float4*)&Bs[kk][q * 32 + j * 4] = *(const float4*)(wp + j * 4);
            }
            __syncthreads();
#pragma unroll
            for (int kk = 0; kk < 32; kk++) {
                float4 a0 = *(const float4*)&As[kk][tm];
                float4 a1 = *(const float4*)&As[kk][tm + 4];
                float4 b0 = *(const float4*)&Bs[kk][tn];
                float4 b1 = *(const float4*)&Bs[kk][tn + 4];
                unsigned long long bp0 = pack2(b0.x, b0.y);
                unsigned long long bp1 = pack2(b0.z, b0.w);
                unsigned long long bp2 = pack2(b1.x, b1.y);
                unsigned long long bp3 = pack2(b1.z, b1.w);
                float af[8] = {a0.x, a0.y, a0.z, a0.w, a1.x, a1.y, a1.z, a1.w};
#pragma unroll
                for (int i = 0; i < 8; i++) {
                    unsigned long long ap = pack2(af[i], af[i]);
                    ffma2(acc[i][0], ap, bp0);
                    ffma2(acc[i][1], ap, bp1);
                    ffma2(acc[i][2], ap, bp2);
                    ffma2(acc[i][3], ap, bp3);
                }
            }
            __syncthreads();
        }
    }

    // Epilogue
    float bb[8], gg[8], be[8];
#pragma unroll
    for (int j = 0; j < 8; j++) bb[j] = bias[tn + j];
    if (FUSE) {
#pragma unroll
        for (int j = 0; j < 8; j++) { gg[j] = gamma[tn + j]; be[j] = beta[tn + j]; }
    }
#pragma unroll
    for (int i = 0; i < 8; i++) {
        int row = bm + tm + i;
        float4 x0 = *(const float4*)&X[row * Dd + tn];
        float4 x1 = *(const float4*)&X[row * Dd + tn + 4];
        float xv[8] = {x0.x, x0.y, x0.z, x0.w, x1.x, x1.y, x1.z, x1.w};
#pragma unroll
        for (int j = 0; j < 4; j++) {
            float lo, hi;
            unpack2(acc[i][j], lo, hi);
            xv[2*j]   += lo + bb[2*j];
            xv[2*j+1] += hi + bb[2*j+1];
        }
        x0 = make_float4(xv[0], xv[1], xv[2], xv[3]);
        x1 = make_float4(xv[4], xv[5], xv[6], xv[7]);
        *(float4*)&X[row * Dd + tn]     = x0;
        *(float4*)&X[row * Dd + tn + 4] = x1;
        if (FUSE) {
            float s = 0.f, s2 = 0.f;
#pragma unroll
            for (int j = 0; j < 8; j++) { s += xv[j]; s2 += xv[j] * xv[j]; }
            // row is spread across the 16 tcol lanes of this half-warp
#pragma unroll
            for (int o = 1; o <= 8; o <<= 1) {
                s  += __shfl_xor_sync(0xffffffffu, s, o);
                s2 += __shfl_xor_sync(0xffffffffu, s2, o);
            }
            float mu  = s * (1.0f / 128.0f);
            float var = s2 * (1.0f / 128.0f) - mu * mu;
            float rs  = rsqrtf(var + 1e-5f);
            float hv[8];
#pragma unroll
            for (int j = 0; j < 8; j++) {
                float t = (xv[j] - mu) * rs * gg[j] + be[j];
                hv[j] = 0.5f * t * (1.0f + erff(t * 0.70710678118654752f));
            }
            *(float4*)&g_h[row * Dd + tn]     = make_float4(hv[0], hv[1], hv[2], hv[3]);
            *(float4*)&g_h[row * Dd + tn + 4] = make_float4(hv[4], hv[5], hv[6], hv[7]);
        }
    }
}

// ---------------------------------------------------------------------------
extern "C" void kernel_launch(void* const* d_in, const int* in_sizes, int n_in,
                              void* d_out, int out_size) {
    const float* elements = (const float*)d_in[0];
    const float* ln_gamma = (const float*)d_in[1];
    const float* ln_beta  = (const float*)d_in[2];
    const float* w_nei    = (const float*)d_in[3];
    const float* b_nei    = (const float*)d_in[4];
    const float* w_root   = (const float*)d_in[5];
    const int*   edges    = (const int*)d_in[6];
    float* x = (float*)d_out;

    int E = in_sizes[6] / 2;
    const int* src = edges;
    const int* dst = edges + E;

    tree1_kernel<<<Bb * 32, Dd>>>(elements);
    tree2_kernel<<<Bb, Dd>>>();
    offsets_kernel<<<(E + 255) / 256, 256>>>(dst, E);
    encx_kernel<<<BN, Dd>>>(x, ln_gamma, ln_beta);

    // layer 0 (gemm fuses LN+GELU for layer 1 into its epilogue)
    agg_kernel<<<BN + HEAVY_W, Dd>>>(src);
    aggfix_kernel<<<Bb * HEAVY_PER_B, Dd>>>();
    gemm_kernel<true><<<BN / 64, 128>>>(w_nei, w_root, b_nei,
                                        ln_gamma + Dd, ln_beta + Dd, x);

    // layer 1 (final — no fused LN)
    agg_kernel<<<BN + HEAVY_W, Dd>>>(src);
    aggfix_kernel<<<Bb * HEAVY_PER_B, Dd>>>();
    gemm_kernel<false><<<BN / 64, 128>>>(w_nei + Dd * Dd, w_root + Dd * Dd,
                                         b_nei + Dd, nullptr, nullptr, x);
}